// round 4
// baseline (speedup 1.0000x reference)
#include <cuda_runtime.h>
#include <cstdint>

#define NB 4
#define NN 4096
#define ND 16
#define KK 10
#define TT 12
#define RPB 16          // rows per block
#define TILE_M 256      // m-tile held in shared
#define FULLM 0xFFFFFFFFu

typedef unsigned long long u64;

// state embeddings: [B][N][D]
__device__ float g_emb[NB * NN * ND];

// ---------------------------------------------------------------------------
// f32x2 packed helpers (Blackwell FFMA2 path, PTX-only)
// ---------------------------------------------------------------------------
__device__ __forceinline__ u64 mul2(u64 a, u64 b) {
    u64 d; asm("mul.rn.f32x2 %0, %1, %2;" : "=l"(d) : "l"(a), "l"(b)); return d;
}
__device__ __forceinline__ u64 fma2(u64 a, u64 b, u64 c) {
    u64 d; asm("fma.rn.f32x2 %0, %1, %2, %3;" : "=l"(d) : "l"(a), "l"(b), "l"(c)); return d;
}
__device__ __forceinline__ u64 add2(u64 a, u64 b) {
    u64 d; asm("add.rn.f32x2 %0, %1, %2;" : "=l"(d) : "l"(a), "l"(b)); return d;
}
__device__ __forceinline__ float red2(u64 a) {
    unsigned lo, hi;
    asm("mov.b64 {%0, %1}, %2;" : "=r"(lo), "=r"(hi) : "l"(a));
    return __uint_as_float(lo) + __uint_as_float(hi);
}
__device__ __forceinline__ float val_of(u64 e) {
    return __uint_as_float((unsigned)(e >> 32));
}

// ---------------------------------------------------------------------------
// Kernel 1: state_emb[b,n,j] = tanh(x[b,T-1,n,0] * W[j] + bfc[j])
// ---------------------------------------------------------------------------
__global__ void emb_kernel(const float* __restrict__ x,
                           const float* __restrict__ W,
                           const float* __restrict__ bfc) {
    int i = blockIdx.x * blockDim.x + threadIdx.x;   // 0 .. B*N-1
    if (i >= NB * NN) return;
    int b = i >> 12;
    int n = i & (NN - 1);
    float xv = x[((size_t)b * TT + (TT - 1)) * NN + n];
    float4* dst = reinterpret_cast<float4*>(&g_emb[(size_t)i * ND]);
#pragma unroll
    for (int j4 = 0; j4 < 4; j4++) {
        float4 o;
        o.x = tanhf(fmaf(xv, W[j4 * 4 + 0], bfc[j4 * 4 + 0]));
        o.y = tanhf(fmaf(xv, W[j4 * 4 + 1], bfc[j4 * 4 + 1]));
        o.z = tanhf(fmaf(xv, W[j4 * 4 + 2], bfc[j4 * 4 + 2]));
        o.w = tanhf(fmaf(xv, W[j4 * 4 + 3], bfc[j4 * 4 + 3]));
        dst[j4] = o;
    }
}

// ---------------------------------------------------------------------------
// Warp-collective insert of candidates (ballot mask msk, per-lane score s)
// into the distributed sorted top-10 (lane k holds k-th largest, k<10).
// Candidate index = mbase + src_lane. Stale candidates (pos==10) are no-ops.
// ---------------------------------------------------------------------------
__device__ __forceinline__ void warp_insert(u64& ent, unsigned msk, float s,
                                            unsigned mbase, int lane) {
    while (msk) {
        int src = __ffs(msk) - 1;
        msk &= msk - 1;
        float pv = __shfl_sync(FULLM, s, src);
        u64 p = ((u64)__float_as_uint(pv) << 32) | (u64)(mbase + src);
        unsigned gmask = __ballot_sync(FULLM, ent > p) & 0x3FFu;
        int pos = __popc(gmask);
        u64 shifted = __shfl_up_sync(FULLM, ent, 1);
        if (lane >= pos && lane < KK) ent = (lane == pos) ? p : shifted;
    }
}

// ---------------------------------------------------------------------------
// Kernel 2: fused A_dyn rows + exact warp-wide top-10 + softmax + output
// Grid: (NN/RPB, NB), 256 threads. Warp g owns rows 2g, 2g+1.
// Filter is batched: one ballot per row per 128-m group (4 m per lane).
// ---------------------------------------------------------------------------
__global__ __launch_bounds__(256, 2) void fused_kernel(
    const float* __restrict__ Aphys,
    const float* __restrict__ alpha_p,
    float* __restrict__ out) {
    __shared__ float4 tile4[TILE_M * 5];     // stride-5 float4 -> conflict-free
    __shared__ u64 shtop[RPB][KK];
    __shared__ float sh_emb[RPB * ND];
    __shared__ float sh_base[RPB], sh_c1[RPB], sh_vmax[RPB];

    const int t = threadIdx.x;
    const int lane = t & 31;
    const int g = t >> 5;
    const int b = blockIdx.y;
    const int n0 = blockIdx.x * RPB;

    const float alpha = *alpha_p;
    const float a = 1.f / (1.f + expf(-alpha));
    const float oma = 1.f - a;

    // load this block's row embeddings
    sh_emb[t] = g_emb[((size_t)b * NN + n0 + (t >> 4)) * ND + (t & 15)];
    __syncthreads();

    // packed (even-d, odd-d) embedding pairs for this warp's 2 rows
    const int rA = 2 * g, rB = 2 * g + 1;
    u64 eA[8], eB[8];
    {
        const u64* pa = reinterpret_cast<const u64*>(&sh_emb[rA * ND]);
        const u64* pb = reinterpret_cast<const u64*>(&sh_emb[rB * ND]);
#pragma unroll
        for (int j = 0; j < 8; j++) { eA[j] = pa[j]; eB[j] = pb[j]; }
    }

    u64 entA = 0ULL, entB = 0ULL;     // distributed top-10 (lanes 0..9)
    float thrA = 0.f, thrB = 0.f;     // value of current 10th largest

    const float4* emb4 = reinterpret_cast<const float4*>(g_emb) + (size_t)b * NN * 4;

    for (int tile = 0; tile < NN / TILE_M; tile++) {
        __syncthreads();
        {   // cooperative stage: thread t loads emb row (tile*256 + t)
            const float4* src = emb4 + (size_t)(tile * TILE_M + t) * 4;
            float4 v0 = src[0], v1 = src[1], v2 = src[2], v3 = src[3];
            tile4[t * 5 + 0] = v0;
            tile4[t * 5 + 1] = v1;
            tile4[t * 5 + 2] = v2;
            tile4[t * 5 + 3] = v3;
        }
        __syncthreads();

#pragma unroll
        for (int grp = 0; grp < TILE_M / 128; grp++) {
            float sA[4], sB[4];
#pragma unroll
            for (int sub = 0; sub < 4; sub++) {
                const int ml = grp * 128 + sub * 32 + lane;
                const ulonglong2* q =
                    reinterpret_cast<const ulonglong2*>(tile4 + ml * 5);
                ulonglong2 q0 = q[0], q1 = q[1], q2 = q[2], q3 = q[3];

                u64 aP = mul2(eA[0], q0.x);
                u64 aQ = mul2(eA[1], q0.y);
                u64 bP = mul2(eB[0], q0.x);
                u64 bQ = mul2(eB[1], q0.y);
                aP = fma2(eA[2], q1.x, aP);  aQ = fma2(eA[3], q1.y, aQ);
                bP = fma2(eB[2], q1.x, bP);  bQ = fma2(eB[3], q1.y, bQ);
                aP = fma2(eA[4], q2.x, aP);  aQ = fma2(eA[5], q2.y, aQ);
                bP = fma2(eB[4], q2.x, bP);  bQ = fma2(eB[5], q2.y, bQ);
                aP = fma2(eA[6], q3.x, aP);  aQ = fma2(eA[7], q3.y, aQ);
                bP = fma2(eB[6], q3.x, bP);  bQ = fma2(eB[7], q3.y, bQ);
                sA[sub] = red2(add2(aP, aQ));
                sB[sub] = red2(add2(bP, bQ));
            }

            const unsigned mbase = (unsigned)(tile * TILE_M + grp * 128);

            float vA = fmaxf(fmaxf(sA[0], sA[1]), fmaxf(sA[2], sA[3]));
            if (__ballot_sync(FULLM, vA > thrA)) {
#pragma unroll
                for (int sub = 0; sub < 4; sub++) {
                    unsigned msk = __ballot_sync(FULLM, sA[sub] > thrA);
                    if (msk) {
                        warp_insert(entA, msk, sA[sub], mbase + sub * 32, lane);
                        thrA = __uint_as_float(
                            (unsigned)(__shfl_sync(FULLM, entA, KK - 1) >> 32));
                    }
                }
            }
            float vB = fmaxf(fmaxf(sB[0], sB[1]), fmaxf(sB[2], sB[3]));
            if (__ballot_sync(FULLM, vB > thrB)) {
#pragma unroll
                for (int sub = 0; sub < 4; sub++) {
                    unsigned msk = __ballot_sync(FULLM, sB[sub] > thrB);
                    if (msk) {
                        warp_insert(entB, msk, sB[sub], mbase + sub * 32, lane);
                        thrB = __uint_as_float(
                            (unsigned)(__shfl_sync(FULLM, entB, KK - 1) >> 32));
                    }
                }
            }
        }
    }

    // publish warp-wide sorted top-10 (already distributed; no merge needed)
    if (lane < KK) {
        shtop[rA][lane] = entA;
        shtop[rB][lane] = entB;
    }
    __syncwarp();

    // per-row softmax constants (lane 0 of each warp handles its 2 rows)
    if (lane == 0) {
#pragma unroll
        for (int rr = 0; rr < 2; rr++) {
            int r = rA + rr;
            float vmax = val_of(shtop[r][0]);   // >= 0
            float s = 0.f;
#pragma unroll
            for (int k = 0; k < KK; k++) s += expf(val_of(shtop[r][k]) - vmax);
            float S = s + (float)(NN - KK) * expf(-vmax);
            float c1 = oma / S;
            sh_c1[r] = c1;
            sh_vmax[r] = vmax;
            sh_base[r] = c1 * expf(-vmax);
        }
    }
    __syncthreads();

    // Phase 3: out = a*A_phys + base for all m (coalesced float4, streaming st)
    const float4* ap_base = reinterpret_cast<const float4*>(Aphys);
    float4* out4 = reinterpret_cast<float4*>(out) + (size_t)b * NN * (NN / 4);
    for (int r = 0; r < RPB; r++) {
        int row = n0 + r;
        float base = sh_base[r];
        const float4* ap = ap_base + (size_t)row * (NN / 4);
        float4* op = out4 + (size_t)row * (NN / 4);
#pragma unroll
        for (int u = 0; u < (NN / 4) / 256; u++) {
            int i = u * 256 + t;
            float4 v = ap[i];
            float4 o;
            o.x = fmaf(a, v.x, base);
            o.y = fmaf(a, v.y, base);
            o.z = fmaf(a, v.z, base);
            o.w = fmaf(a, v.w, base);
            __stcs(&op[i], o);
        }
    }
    __syncthreads();

    // Phase 4: scatter fix-ups for top-K entries (skip zero placeholders)
    if (t < RPB * KK) {
        int r = t / KK, k = t - r * KK;
        u64 e = shtop[r][k];
        if (e != 0ULL) {
            unsigned idx = (unsigned)e;
            float v = val_of(e);
            int row = n0 + r;
            float pv = Aphys[(size_t)row * NN + idx];
            out[((size_t)b * NN + row) * NN + idx] =
                fmaf(a, pv, sh_c1[r] * expf(v - sh_vmax[r]));
        }
    }
}

// ---------------------------------------------------------------------------
extern "C" void kernel_launch(void* const* d_in, const int* in_sizes, int n_in,
                              void* d_out, int out_size) {
    const float* x     = (const float*)d_in[0];
    const float* Aphys = (const float*)d_in[1];
    const float* Wfc   = (const float*)d_in[2];
    const float* bfc   = (const float*)d_in[3];
    const float* alpha = (const float*)d_in[4];
    float* out = (float*)d_out;

    emb_kernel<<<(NB * NN + 255) / 256, 256>>>(x, Wfc, bfc);
    dim3 grid(NN / RPB, NB);
    fused_kernel<<<grid, 256>>>(Aphys, alpha, out);
}

// round 5
// speedup vs baseline: 1.2475x; 1.2475x over previous
#include <cuda_runtime.h>
#include <cstdint>

#define NB 4
#define NN 4096
#define ND 16
#define KK 10
#define TT 12
#define RPW 4           // rows per warp
#define RPB 32          // rows per block (8 warps * RPW)
#define TILE_M 256      // m-tile held in shared
#define FULLM 0xFFFFFFFFu

typedef unsigned long long u64;

// state embeddings: [B][N][D]
__device__ float g_emb[NB * NN * ND];

// ---------------------------------------------------------------------------
// f32x2 packed helpers (Blackwell FFMA2 path, PTX-only)
// ---------------------------------------------------------------------------
__device__ __forceinline__ u64 mul2(u64 a, u64 b) {
    u64 d; asm("mul.rn.f32x2 %0, %1, %2;" : "=l"(d) : "l"(a), "l"(b)); return d;
}
__device__ __forceinline__ u64 fma2(u64 a, u64 b, u64 c) {
    u64 d; asm("fma.rn.f32x2 %0, %1, %2, %3;" : "=l"(d) : "l"(a), "l"(b), "l"(c)); return d;
}
__device__ __forceinline__ u64 add2(u64 a, u64 b) {
    u64 d; asm("add.rn.f32x2 %0, %1, %2;" : "=l"(d) : "l"(a), "l"(b)); return d;
}
__device__ __forceinline__ float red2(u64 a) {
    unsigned lo, hi;
    asm("mov.b64 {%0, %1}, %2;" : "=r"(lo), "=r"(hi) : "l"(a));
    return __uint_as_float(lo) + __uint_as_float(hi);
}
__device__ __forceinline__ float val_of(u64 e) {
    return __uint_as_float((unsigned)(e >> 32));
}

// ---------------------------------------------------------------------------
// Kernel 1: state_emb[b,n,j] = tanh(x[b,T-1,n,0] * W[j] + bfc[j])
// ---------------------------------------------------------------------------
__global__ void emb_kernel(const float* __restrict__ x,
                           const float* __restrict__ W,
                           const float* __restrict__ bfc) {
    int i = blockIdx.x * blockDim.x + threadIdx.x;   // 0 .. B*N-1
    if (i >= NB * NN) return;
    int b = i >> 12;
    int n = i & (NN - 1);
    float xv = x[((size_t)b * TT + (TT - 1)) * NN + n];
    float4* dst = reinterpret_cast<float4*>(&g_emb[(size_t)i * ND]);
#pragma unroll
    for (int j4 = 0; j4 < 4; j4++) {
        float4 o;
        o.x = tanhf(fmaf(xv, W[j4 * 4 + 0], bfc[j4 * 4 + 0]));
        o.y = tanhf(fmaf(xv, W[j4 * 4 + 1], bfc[j4 * 4 + 1]));
        o.z = tanhf(fmaf(xv, W[j4 * 4 + 2], bfc[j4 * 4 + 2]));
        o.w = tanhf(fmaf(xv, W[j4 * 4 + 3], bfc[j4 * 4 + 3]));
        dst[j4] = o;
    }
}

// ---------------------------------------------------------------------------
// Warp-collective insert of candidates (ballot mask msk, per-lane score s)
// into the distributed sorted top-10 (lane k holds k-th largest, k<10).
// Candidate index = mbase + src_lane. Stale candidates (pos==10) are no-ops.
// ---------------------------------------------------------------------------
__device__ __forceinline__ void warp_insert(u64& ent, unsigned msk, float s,
                                            unsigned mbase, int lane) {
    while (msk) {
        int src = __ffs(msk) - 1;
        msk &= msk - 1;
        float pv = __shfl_sync(FULLM, s, src);
        u64 p = ((u64)__float_as_uint(pv) << 32) | (u64)(mbase + src);
        unsigned gmask = __ballot_sync(FULLM, ent > p) & 0x3FFu;
        int pos = __popc(gmask);
        u64 shifted = __shfl_up_sync(FULLM, ent, 1);
        if (lane >= pos && lane < KK) ent = (lane == pos) ? p : shifted;
    }
}

// ---------------------------------------------------------------------------
// Kernel 2: fused A_dyn rows + exact warp-wide top-10 + softmax + output
// Grid: (NN/RPB, NB), 256 threads. Warp g owns rows 4g..4g+3.
// ---------------------------------------------------------------------------
__global__ __launch_bounds__(256, 2) void fused_kernel(
    const float* __restrict__ Aphys,
    const float* __restrict__ alpha_p,
    float* __restrict__ out) {
    __shared__ float4 tile4[TILE_M * 5];     // stride-5 float4 -> conflict-free
    __shared__ u64 shtop[RPB][KK];
    __shared__ float sh_emb[RPB * ND];
    __shared__ float sh_base[RPB], sh_c1[RPB], sh_vmax[RPB];

    const int t = threadIdx.x;
    const int lane = t & 31;
    const int g = t >> 5;
    const int b = blockIdx.y;
    const int n0 = blockIdx.x * RPB;

    const float alpha = *alpha_p;
    const float a = 1.f / (1.f + expf(-alpha));
    const float oma = 1.f - a;

    // load this block's row embeddings (512 floats)
    sh_emb[t] = g_emb[((size_t)b * NN + n0 + (t >> 4)) * ND + (t & 15)];
    sh_emb[t + 256] =
        g_emb[((size_t)b * NN + n0 + ((t + 256) >> 4)) * ND + (t & 15)];
    __syncthreads();

    // packed (even-d, odd-d) embedding pairs for this warp's 4 rows
    const int r0 = RPW * g;
    u64 e[RPW][8];
#pragma unroll
    for (int r = 0; r < RPW; r++) {
        const u64* p = reinterpret_cast<const u64*>(&sh_emb[(r0 + r) * ND]);
#pragma unroll
        for (int j = 0; j < 8; j++) e[r][j] = p[j];
    }

    u64 ent[RPW];                     // distributed top-10 (lanes 0..9)
    float thr[RPW];                   // value of current 10th largest
#pragma unroll
    for (int r = 0; r < RPW; r++) { ent[r] = 0ULL; thr[r] = 0.f; }

    const float4* emb4 = reinterpret_cast<const float4*>(g_emb) + (size_t)b * NN * 4;

    for (int tile = 0; tile < NN / TILE_M; tile++) {
        __syncthreads();
        {   // cooperative stage: thread t loads emb row (tile*256 + t)
            const float4* src = emb4 + (size_t)(tile * TILE_M + t) * 4;
            float4 v0 = src[0], v1 = src[1], v2 = src[2], v3 = src[3];
            tile4[t * 5 + 0] = v0;
            tile4[t * 5 + 1] = v1;
            tile4[t * 5 + 2] = v2;
            tile4[t * 5 + 3] = v3;
        }
        __syncthreads();

#pragma unroll
        for (int it = 0; it < TILE_M / 32; it++) {
            const int ml = it * 32 + lane;
            const ulonglong2* q =
                reinterpret_cast<const ulonglong2*>(tile4 + ml * 5);
            ulonglong2 q0 = q[0], q1 = q[1], q2 = q[2], q3 = q[3];

            float s[RPW];
            u64 P[RPW], Q[RPW];
#pragma unroll
            for (int r = 0; r < RPW; r++) {
                P[r] = mul2(e[r][0], q0.x);
                Q[r] = mul2(e[r][1], q0.y);
            }
#pragma unroll
            for (int r = 0; r < RPW; r++) {
                P[r] = fma2(e[r][2], q1.x, P[r]);
                Q[r] = fma2(e[r][3], q1.y, Q[r]);
            }
#pragma unroll
            for (int r = 0; r < RPW; r++) {
                P[r] = fma2(e[r][4], q2.x, P[r]);
                Q[r] = fma2(e[r][5], q2.y, Q[r]);
            }
#pragma unroll
            for (int r = 0; r < RPW; r++) {
                P[r] = fma2(e[r][6], q3.x, P[r]);
                Q[r] = fma2(e[r][7], q3.y, Q[r]);
            }
#pragma unroll
            for (int r = 0; r < RPW; r++) s[r] = red2(add2(P[r], Q[r]));

            const unsigned mbase = (unsigned)(tile * TILE_M + it * 32);
#pragma unroll
            for (int r = 0; r < RPW; r++) {
                unsigned msk = __ballot_sync(FULLM, s[r] > thr[r]);
                if (msk) {
                    warp_insert(ent[r], msk, s[r], mbase, lane);
                    thr[r] = __uint_as_float(
                        (unsigned)(__shfl_sync(FULLM, ent[r], KK - 1) >> 32));
                }
            }
        }
    }

    // publish warp-wide sorted top-10 (already distributed; no merge needed)
    if (lane < KK) {
#pragma unroll
        for (int r = 0; r < RPW; r++) shtop[r0 + r][lane] = ent[r];
    }
    __syncwarp();

    // per-row softmax constants (lane 0 of each warp handles its 4 rows)
    if (lane == 0) {
#pragma unroll
        for (int rr = 0; rr < RPW; rr++) {
            int r = r0 + rr;
            float vmax = val_of(shtop[r][0]);   // >= 0
            float s = 0.f;
#pragma unroll
            for (int k = 0; k < KK; k++) s += expf(val_of(shtop[r][k]) - vmax);
            float S = s + (float)(NN - KK) * expf(-vmax);
            float c1 = oma / S;
            sh_c1[r] = c1;
            sh_vmax[r] = vmax;
            sh_base[r] = c1 * expf(-vmax);
        }
    }
    __syncthreads();

    // Phase 3: out = a*A_phys + base for all m (coalesced float4, streaming st)
    const float4* ap_base = reinterpret_cast<const float4*>(Aphys);
    float4* out4 = reinterpret_cast<float4*>(out) + (size_t)b * NN * (NN / 4);
    for (int r = 0; r < RPB; r++) {
        int row = n0 + r;
        float base = sh_base[r];
        const float4* ap = ap_base + (size_t)row * (NN / 4);
        float4* op = out4 + (size_t)row * (NN / 4);
#pragma unroll
        for (int u = 0; u < (NN / 4) / 256; u++) {
            int i = u * 256 + t;
            float4 v = ap[i];
            float4 o;
            o.x = fmaf(a, v.x, base);
            o.y = fmaf(a, v.y, base);
            o.z = fmaf(a, v.z, base);
            o.w = fmaf(a, v.w, base);
            __stcs(&op[i], o);
        }
    }
    __syncthreads();

    // Phase 4: scatter fix-ups for top-K entries (skip zero placeholders)
    for (int i = t; i < RPB * KK; i += 256) {
        int r = i / KK, k = i - r * KK;
        u64 ee = shtop[r][k];
        if (ee != 0ULL) {
            unsigned idx = (unsigned)ee;
            float v = val_of(ee);
            int row = n0 + r;
            float pv = Aphys[(size_t)row * NN + idx];
            out[((size_t)b * NN + row) * NN + idx] =
                fmaf(a, pv, sh_c1[r] * expf(v - sh_vmax[r]));
        }
    }
}

// ---------------------------------------------------------------------------
extern "C" void kernel_launch(void* const* d_in, const int* in_sizes, int n_in,
                              void* d_out, int out_size) {
    const float* x     = (const float*)d_in[0];
    const float* Aphys = (const float*)d_in[1];
    const float* Wfc   = (const float*)d_in[2];
    const float* bfc   = (const float*)d_in[3];
    const float* alpha = (const float*)d_in[4];
    float* out = (float*)d_out;

    emb_kernel<<<(NB * NN + 255) / 256, 256>>>(x, Wfc, bfc);
    dim3 grid(NN / RPB, NB);
    fused_kernel<<<grid, 256>>>(Aphys, alpha, out);
}

// round 6
// speedup vs baseline: 1.2605x; 1.0104x over previous
#include <cuda_runtime.h>
#include <cstdint>

#define NB 4
#define NN 4096
#define ND 16
#define KK 10
#define TT 12
#define RPW 4           // rows per warp
#define RPB 32          // rows per block (8 warps * RPW)
#define TILE_M 512      // m-tile held in shared (double-buffered)
#define ITS (TILE_M / 32)
#define FULLM 0xFFFFFFFFu

typedef unsigned long long u64;

// state embeddings: [B][N][D]
__device__ float g_emb[NB * NN * ND];

// ---------------------------------------------------------------------------
// f32x2 packed helpers (Blackwell FFMA2 path, PTX-only)
// ---------------------------------------------------------------------------
__device__ __forceinline__ u64 mul2(u64 a, u64 b) {
    u64 d; asm("mul.rn.f32x2 %0, %1, %2;" : "=l"(d) : "l"(a), "l"(b)); return d;
}
__device__ __forceinline__ u64 fma2(u64 a, u64 b, u64 c) {
    u64 d; asm("fma.rn.f32x2 %0, %1, %2, %3;" : "=l"(d) : "l"(a), "l"(b), "l"(c)); return d;
}
__device__ __forceinline__ float red2(u64 a) {
    unsigned lo, hi;
    asm("mov.b64 {%0, %1}, %2;" : "=r"(lo), "=r"(hi) : "l"(a));
    return __uint_as_float(lo) + __uint_as_float(hi);
}
__device__ __forceinline__ float val_of(u64 e) {
    return __uint_as_float((unsigned)(e >> 32));
}

__device__ __forceinline__ void cp_async16(void* smem_dst, const void* gsrc) {
    unsigned sa = (unsigned)__cvta_generic_to_shared(smem_dst);
    asm volatile("cp.async.ca.shared.global [%0], [%1], 16;\n"
                 :: "r"(sa), "l"(gsrc));
}
__device__ __forceinline__ void cp_commit() {
    asm volatile("cp.async.commit_group;\n");
}
template <int N>
__device__ __forceinline__ void cp_wait() {
    asm volatile("cp.async.wait_group %0;\n" :: "n"(N));
}

// ---------------------------------------------------------------------------
// Kernel 1: state_emb[b,n,j] = tanh(x[b,T-1,n,0] * W[j] + bfc[j])
// ---------------------------------------------------------------------------
__global__ void emb_kernel(const float* __restrict__ x,
                           const float* __restrict__ W,
                           const float* __restrict__ bfc) {
    int i = blockIdx.x * blockDim.x + threadIdx.x;   // 0 .. B*N-1
    if (i >= NB * NN) return;
    int b = i >> 12;
    int n = i & (NN - 1);
    float xv = x[((size_t)b * TT + (TT - 1)) * NN + n];
    float4* dst = reinterpret_cast<float4*>(&g_emb[(size_t)i * ND]);
#pragma unroll
    for (int j4 = 0; j4 < 4; j4++) {
        float4 o;
        o.x = tanhf(fmaf(xv, W[j4 * 4 + 0], bfc[j4 * 4 + 0]));
        o.y = tanhf(fmaf(xv, W[j4 * 4 + 1], bfc[j4 * 4 + 1]));
        o.z = tanhf(fmaf(xv, W[j4 * 4 + 2], bfc[j4 * 4 + 2]));
        o.w = tanhf(fmaf(xv, W[j4 * 4 + 3], bfc[j4 * 4 + 3]));
        dst[j4] = o;
    }
}

// ---------------------------------------------------------------------------
// Warp-collective insert of candidates (ballot mask msk, per-lane score s)
// into the distributed sorted top-10 (lane k holds k-th largest, k<10).
// Candidate index = mbase + src_lane. Stale candidates (pos==10) are no-ops.
// ---------------------------------------------------------------------------
__device__ __forceinline__ void warp_insert(u64& ent, unsigned msk, float s,
                                            unsigned mbase, int lane) {
    while (msk) {
        int src = __ffs(msk) - 1;
        msk &= msk - 1;
        float pv = __shfl_sync(FULLM, s, src);
        u64 p = ((u64)__float_as_uint(pv) << 32) | (u64)(mbase + src);
        unsigned gmask = __ballot_sync(FULLM, ent > p) & 0x3FFu;
        int pos = __popc(gmask);
        u64 shifted = __shfl_up_sync(FULLM, ent, 1);
        if (lane >= pos && lane < KK) ent = (lane == pos) ? p : shifted;
    }
}

// ---------------------------------------------------------------------------
// Kernel 2: fused A_dyn rows + exact warp-wide top-10 + softmax + output
// Grid: (NN/RPB, NB), 256 threads. Warp g owns rows 4g..4g+3.
// cp.async double-buffered m-tiles; q software-pipelined within tile.
// ---------------------------------------------------------------------------
__global__ __launch_bounds__(256, 2) void fused_kernel(
    const float* __restrict__ Aphys,
    const float* __restrict__ alpha_p,
    float* __restrict__ out) {
    __shared__ __align__(16) float4 tile4[2][TILE_M * 5];  // stride-5 f4
    __shared__ u64 shtop[RPB][KK];
    __shared__ __align__(16) float sh_emb[RPB * ND];
    __shared__ float sh_base[RPB], sh_c1[RPB], sh_vmax[RPB];

    const int t = threadIdx.x;
    const int lane = t & 31;
    const int g = t >> 5;
    const int b = blockIdx.y;
    const int n0 = blockIdx.x * RPB;

    const float alpha = *alpha_p;
    const float a = 1.f / (1.f + expf(-alpha));
    const float oma = 1.f - a;

    // load this block's row embeddings (512 floats)
    sh_emb[t] = g_emb[((size_t)b * NN + n0 + (t >> 4)) * ND + (t & 15)];
    sh_emb[t + 256] =
        g_emb[((size_t)b * NN + n0 + ((t + 256) >> 4)) * ND + (t & 15)];
    __syncthreads();

    // packed (even-d, odd-d) embedding pairs for this warp's 4 rows
    const int r0 = RPW * g;
    u64 e[RPW][8];
#pragma unroll
    for (int r = 0; r < RPW; r++) {
        const u64* p = reinterpret_cast<const u64*>(&sh_emb[(r0 + r) * ND]);
#pragma unroll
        for (int j = 0; j < 8; j++) e[r][j] = p[j];
    }

    u64 ent[RPW];                     // distributed top-10 (lanes 0..9)
    float thr[RPW];                   // value of current 10th largest
#pragma unroll
    for (int r = 0; r < RPW; r++) { ent[r] = 0ULL; thr[r] = 0.f; }

    const float* embf = g_emb + (size_t)b * NN * ND;

    // ---- stage tile 0 (each thread: 2 rows x 4 16B-chunks) ----
    {
#pragma unroll
        for (int rr = 0; rr < 2; rr++) {
            int mr = rr * 256 + t;
            const float* src = embf + (size_t)mr * ND;
#pragma unroll
            for (int c = 0; c < 4; c++)
                cp_async16(&tile4[0][mr * 5 + c], src + c * 4);
        }
        cp_commit();
    }

    const int NTILES = NN / TILE_M;
    for (int tile = 0; tile < NTILES; tile++) {
        // stage next tile into other buffer
        if (tile + 1 < NTILES) {
#pragma unroll
            for (int rr = 0; rr < 2; rr++) {
                int mr = rr * 256 + t;
                const float* src = embf + (size_t)((tile + 1) * TILE_M + mr) * ND;
#pragma unroll
                for (int c = 0; c < 4; c++)
                    cp_async16(&tile4[(tile + 1) & 1][mr * 5 + c], src + c * 4);
            }
            cp_commit();
            cp_wait<1>();   // current tile's group done
        } else {
            cp_wait<0>();
        }
        __syncthreads();

        const float4* buf = tile4[tile & 1];

        // software-pipelined q: prefetch it+1 while computing it
        ulonglong2 cq0, cq1, cq2, cq3;
        {
            const ulonglong2* q = reinterpret_cast<const ulonglong2*>(buf + lane * 5);
            cq0 = q[0]; cq1 = q[1]; cq2 = q[2]; cq3 = q[3];
        }
#pragma unroll
        for (int it = 0; it < ITS; it++) {
            ulonglong2 nq0, nq1, nq2, nq3;
            if (it + 1 < ITS) {
                const ulonglong2* q = reinterpret_cast<const ulonglong2*>(
                    buf + ((it + 1) * 32 + lane) * 5);
                nq0 = q[0]; nq1 = q[1]; nq2 = q[2]; nq3 = q[3];
            }

            float s[RPW];
#pragma unroll
            for (int r = 0; r < RPW; r++) {
                u64 acc = mul2(e[r][0], cq0.x);
                acc = fma2(e[r][1], cq0.y, acc);
                acc = fma2(e[r][2], cq1.x, acc);
                acc = fma2(e[r][3], cq1.y, acc);
                acc = fma2(e[r][4], cq2.x, acc);
                acc = fma2(e[r][5], cq2.y, acc);
                acc = fma2(e[r][6], cq3.x, acc);
                acc = fma2(e[r][7], cq3.y, acc);
                s[r] = red2(acc);
            }

            const unsigned mbase = (unsigned)(tile * TILE_M + it * 32);
#pragma unroll
            for (int r = 0; r < RPW; r++) {
                unsigned msk = __ballot_sync(FULLM, s[r] > thr[r]);
                if (msk) {
                    warp_insert(ent[r], msk, s[r], mbase, lane);
                    thr[r] = __uint_as_float(
                        (unsigned)(__shfl_sync(FULLM, ent[r], KK - 1) >> 32));
                }
            }

            if (it + 1 < ITS) { cq0 = nq0; cq1 = nq1; cq2 = nq2; cq3 = nq3; }
        }
        __syncthreads();   // done reading buf before restaging it
    }

    // publish warp-wide sorted top-10 (already distributed; no merge needed)
    if (lane < KK) {
#pragma unroll
        for (int r = 0; r < RPW; r++) shtop[r0 + r][lane] = ent[r];
    }
    __syncwarp();

    // per-row softmax constants (lane 0 of each warp handles its 4 rows)
    if (lane == 0) {
#pragma unroll
        for (int rr = 0; rr < RPW; rr++) {
            int r = r0 + rr;
            float vmax = val_of(shtop[r][0]);   // >= 0
            float s = 0.f;
#pragma unroll
            for (int k = 0; k < KK; k++) s += expf(val_of(shtop[r][k]) - vmax);
            float S = s + (float)(NN - KK) * expf(-vmax);
            float c1 = oma / S;
            sh_c1[r] = c1;
            sh_vmax[r] = vmax;
            sh_base[r] = c1 * expf(-vmax);
        }
    }
    __syncthreads();

    // Phase 3: out = a*A_phys + base for all m (coalesced float4, streaming st)
    const float4* ap_base = reinterpret_cast<const float4*>(Aphys);
    float4* out4 = reinterpret_cast<float4*>(out) + (size_t)b * NN * (NN / 4);
    for (int r = 0; r < RPB; r++) {
        int row = n0 + r;
        float base = sh_base[r];
        const float4* ap = ap_base + (size_t)row * (NN / 4);
        float4* op = out4 + (size_t)row * (NN / 4);
#pragma unroll
        for (int u = 0; u < (NN / 4) / 256; u++) {
            int i = u * 256 + t;
            float4 v = ap[i];
            float4 o;
            o.x = fmaf(a, v.x, base);
            o.y = fmaf(a, v.y, base);
            o.z = fmaf(a, v.z, base);
            o.w = fmaf(a, v.w, base);
            __stcs(&op[i], o);
        }
    }
    __syncthreads();

    // Phase 4: scatter fix-ups for top-K entries (skip zero placeholders)
    for (int i = t; i < RPB * KK; i += 256) {
        int r = i / KK, k = i - r * KK;
        u64 ee = shtop[r][k];
        if (ee != 0ULL) {
            unsigned idx = (unsigned)ee;
            float v = val_of(ee);
            int row = n0 + r;
            float pv = Aphys[(size_t)row * NN + idx];
            out[((size_t)b * NN + row) * NN + idx] =
                fmaf(a, pv, sh_c1[r] * expf(v - sh_vmax[r]));
        }
    }
}

// ---------------------------------------------------------------------------
extern "C" void kernel_launch(void* const* d_in, const int* in_sizes, int n_in,
                              void* d_out, int out_size) {
    const float* x     = (const float*)d_in[0];
    const float* Aphys = (const float*)d_in[1];
    const float* Wfc   = (const float*)d_in[2];
    const float* bfc   = (const float*)d_in[3];
    const float* alpha = (const float*)d_in[4];
    float* out = (float*)d_out;

    emb_kernel<<<(NB * NN + 255) / 256, 256>>>(x, Wfc, bfc);
    dim3 grid(NN / RPB, NB);
    fused_kernel<<<grid, 256>>>(Aphys, alpha, out);
}

// round 7
// speedup vs baseline: 1.2887x; 1.0224x over previous
#include <cuda_runtime.h>
#include <cstdint>

#define NB 4
#define NN 4096
#define ND 16
#define KK 10
#define TT 12
#define RPW 2           // rows per warp (keep e-regs low for occupancy)
#define RPB 16          // rows per block (8 warps * RPW)
#define TILE_M 256      // m-tile held in shared
#define ITS (TILE_M / 32)
#define FULLM 0xFFFFFFFFu

typedef unsigned long long u64;

// state embeddings: [B][N][D]
__device__ float g_emb[NB * NN * ND];
// per-row top-10 packed entries and softmax consts
__device__ u64 g_top[NB * NN * KK];
__device__ float4 g_consts[NB * NN];   // {base, c1, vmax, unused}

// ---------------------------------------------------------------------------
// f32x2 packed helpers (Blackwell FFMA2 path, PTX-only)
// ---------------------------------------------------------------------------
__device__ __forceinline__ u64 mul2(u64 a, u64 b) {
    u64 d; asm("mul.rn.f32x2 %0, %1, %2;" : "=l"(d) : "l"(a), "l"(b)); return d;
}
__device__ __forceinline__ u64 fma2(u64 a, u64 b, u64 c) {
    u64 d; asm("fma.rn.f32x2 %0, %1, %2, %3;" : "=l"(d) : "l"(a), "l"(b), "l"(c)); return d;
}
__device__ __forceinline__ float red2(u64 a) {
    unsigned lo, hi;
    asm("mov.b64 {%0, %1}, %2;" : "=r"(lo), "=r"(hi) : "l"(a));
    return __uint_as_float(lo) + __uint_as_float(hi);
}
__device__ __forceinline__ float val_of(u64 e) {
    return __uint_as_float((unsigned)(e >> 32));
}

// ---------------------------------------------------------------------------
// Kernel 1: state_emb[b,n,j] = tanh(x[b,T-1,n,0] * W[j] + bfc[j])
// ---------------------------------------------------------------------------
__global__ void emb_kernel(const float* __restrict__ x,
                           const float* __restrict__ W,
                           const float* __restrict__ bfc) {
    int i = blockIdx.x * blockDim.x + threadIdx.x;   // 0 .. B*N-1
    if (i >= NB * NN) return;
    int b = i >> 12;
    int n = i & (NN - 1);
    float xv = x[((size_t)b * TT + (TT - 1)) * NN + n];
    float4* dst = reinterpret_cast<float4*>(&g_emb[(size_t)i * ND]);
#pragma unroll
    for (int j4 = 0; j4 < 4; j4++) {
        float4 o;
        o.x = tanhf(fmaf(xv, W[j4 * 4 + 0], bfc[j4 * 4 + 0]));
        o.y = tanhf(fmaf(xv, W[j4 * 4 + 1], bfc[j4 * 4 + 1]));
        o.z = tanhf(fmaf(xv, W[j4 * 4 + 2], bfc[j4 * 4 + 2]));
        o.w = tanhf(fmaf(xv, W[j4 * 4 + 3], bfc[j4 * 4 + 3]));
        dst[j4] = o;
    }
}

// ---------------------------------------------------------------------------
// Warp-collective insert of candidates (ballot mask msk, per-lane score s)
// into the distributed sorted top-10 (lane k holds k-th largest, k<10).
// Candidate index = mbase + src_lane. Stale candidates (pos==10) are no-ops.
// ---------------------------------------------------------------------------
__device__ __forceinline__ void warp_insert(u64& ent, unsigned msk, float s,
                                            unsigned mbase, int lane) {
    while (msk) {
        int src = __ffs(msk) - 1;
        msk &= msk - 1;
        float pv = __shfl_sync(FULLM, s, src);
        u64 p = ((u64)__float_as_uint(pv) << 32) | (u64)(mbase + src);
        unsigned gmask = __ballot_sync(FULLM, ent > p) & 0x3FFu;
        int pos = __popc(gmask);
        u64 shifted = __shfl_up_sync(FULLM, ent, 1);
        if (lane >= pos && lane < KK) ent = (lane == pos) ? p : shifted;
    }
}

// ---------------------------------------------------------------------------
// Kernel 2: top-10 per row + softmax consts -> scratch (NO big output write)
// Grid: (NN/RPB, NB), 256 threads, 4 blocks/SM. Warp g owns rows 2g, 2g+1.
// ---------------------------------------------------------------------------
__global__ __launch_bounds__(256, 4) void topk_kernel(
    const float* __restrict__ alpha_p) {
    __shared__ __align__(16) float4 tile4[TILE_M * 5];  // stride-5 f4

    const int t = threadIdx.x;
    const int lane = t & 31;
    const int g = t >> 5;
    const int b = blockIdx.y;
    const int n0 = blockIdx.x * RPB;

    const float* embf = g_emb + (size_t)b * NN * ND;

    // this warp's 2 row embeddings, packed (even,odd) pairs, via broadcast LDG
    const int rowA = n0 + RPW * g;
    u64 e[RPW][8];
#pragma unroll
    for (int r = 0; r < RPW; r++) {
        const u64* p = reinterpret_cast<const u64*>(embf + (size_t)(rowA + r) * ND);
#pragma unroll
        for (int j = 0; j < 8; j++) e[r][j] = p[j];
    }

    u64 ent[RPW];
    float thr[RPW];
#pragma unroll
    for (int r = 0; r < RPW; r++) { ent[r] = 0ULL; thr[r] = 0.f; }

    for (int tile = 0; tile < NN / TILE_M; tile++) {
        __syncthreads();
        {   // cooperative stage: thread t loads emb row (tile*256 + t)
            const float4* src = reinterpret_cast<const float4*>(
                embf + (size_t)(tile * TILE_M + t) * ND);
            float4 v0 = src[0], v1 = src[1], v2 = src[2], v3 = src[3];
            tile4[t * 5 + 0] = v0;
            tile4[t * 5 + 1] = v1;
            tile4[t * 5 + 2] = v2;
            tile4[t * 5 + 3] = v3;
        }
        __syncthreads();

#pragma unroll
        for (int it = 0; it < ITS; it++) {
            const int ml = it * 32 + lane;
            const ulonglong2* q =
                reinterpret_cast<const ulonglong2*>(tile4 + ml * 5);
            ulonglong2 q0 = q[0], q1 = q[1], q2 = q[2], q3 = q[3];

            float s[RPW];
#pragma unroll
            for (int r = 0; r < RPW; r++) {
                u64 acc = mul2(e[r][0], q0.x);
                acc = fma2(e[r][1], q0.y, acc);
                acc = fma2(e[r][2], q1.x, acc);
                acc = fma2(e[r][3], q1.y, acc);
                acc = fma2(e[r][4], q2.x, acc);
                acc = fma2(e[r][5], q2.y, acc);
                acc = fma2(e[r][6], q3.x, acc);
                acc = fma2(e[r][7], q3.y, acc);
                s[r] = red2(acc);
            }

            const unsigned mbase = (unsigned)(tile * TILE_M + it * 32);
#pragma unroll
            for (int r = 0; r < RPW; r++) {
                unsigned msk = __ballot_sync(FULLM, s[r] > thr[r]);
                if (msk) {
                    warp_insert(ent[r], msk, s[r], mbase, lane);
                    thr[r] = __uint_as_float(
                        (unsigned)(__shfl_sync(FULLM, ent[r], KK - 1) >> 32));
                }
            }
        }
    }

    // epilogue: consts + scratch writes (alpha only touched here)
    const float alpha = *alpha_p;
    const float a = 1.f / (1.f + expf(-alpha));
    const float oma = 1.f - a;

#pragma unroll
    for (int r = 0; r < RPW; r++) {
        const int row = rowA + r;
        // all lanes redundantly compute S via shfl broadcasts (no divergence)
        float vmax = val_of(__shfl_sync(FULLM, ent[r], 0));
        float S = 0.f;
#pragma unroll
        for (int k = 0; k < KK; k++)
            S += expf(val_of(__shfl_sync(FULLM, ent[r], k)) - vmax);
        S += (float)(NN - KK) * expf(-vmax);
        float c1 = oma / S;
        if (lane < KK)
            g_top[((size_t)b * NN + row) * KK + lane] = ent[r];
        if (lane == 0)
            g_consts[(size_t)b * NN + row] =
                make_float4(c1 * expf(-vmax), c1, vmax, 0.f);
    }
}

// ---------------------------------------------------------------------------
// Kernel 3: out[b,row,:] = a*A_phys[row,:] + base, then top-K fix-ups.
// Grid (NB, NN): batch fastest so the 4 batches of a row share L2 for A_phys.
// ---------------------------------------------------------------------------
__global__ __launch_bounds__(256) void write_kernel(
    const float* __restrict__ Aphys,
    const float* __restrict__ alpha_p,
    float* __restrict__ out) {
    const int t = threadIdx.x;
    const int b = blockIdx.x;
    const int row = blockIdx.y;

    const float alpha = *alpha_p;
    const float a = 1.f / (1.f + expf(-alpha));

    float4 c = g_consts[(size_t)b * NN + row];
    const float base = c.x, c1 = c.y, vmax = c.z;

    const float4* ap = reinterpret_cast<const float4*>(Aphys) + (size_t)row * (NN / 4);
    float4* op = reinterpret_cast<float4*>(out) + ((size_t)b * NN + row) * (NN / 4);

#pragma unroll
    for (int u = 0; u < (NN / 4) / 256; u++) {
        int i = u * 256 + t;
        float4 v = ap[i];
        float4 o;
        o.x = fmaf(a, v.x, base);
        o.y = fmaf(a, v.y, base);
        o.z = fmaf(a, v.z, base);
        o.w = fmaf(a, v.w, base);
        __stcs(&op[i], o);
    }
    __syncthreads();

    if (t < KK) {
        u64 e = g_top[((size_t)b * NN + row) * KK + t];
        if (e != 0ULL) {
            unsigned idx = (unsigned)e;
            float v = val_of(e);
            float pv = Aphys[(size_t)row * NN + idx];
            out[((size_t)b * NN + row) * NN + idx] =
                fmaf(a, pv, c1 * expf(v - vmax));
        }
    }
}

// ---------------------------------------------------------------------------
extern "C" void kernel_launch(void* const* d_in, const int* in_sizes, int n_in,
                              void* d_out, int out_size) {
    const float* x     = (const float*)d_in[0];
    const float* Aphys = (const float*)d_in[1];
    const float* Wfc   = (const float*)d_in[2];
    const float* bfc   = (const float*)d_in[3];
    const float* alpha = (const float*)d_in[4];
    float* out = (float*)d_out;

    emb_kernel<<<(NB * NN + 255) / 256, 256>>>(x, Wfc, bfc);
    dim3 grid2(NN / RPB, NB);
    topk_kernel<<<grid2, 256>>>(alpha);
    dim3 grid3(NB, NN);
    write_kernel<<<grid3, 256>>>(Aphys, alpha, out);
}